// round 11
// baseline (speedup 1.0000x reference)
#include <cuda_runtime.h>
#include <cuda_bf16.h>
#include <cstdint>

// Problem constants (fixed shapes)
#define CELLS 4096
#define BATCH 256
#define FIN   160
#define FHID  192
#define KC    32          // K-chunk (5 chunks of 32 = 160)
#define NCHUNK 5
#define NTHREADS 512

// bf16 operand buffer (single): padded stride 40 bf16 (80 B) -> conflict-free
// for ldmatrix 8-row phases and convert STS.
#define ASTRIDE 80        // bytes per bf16 row (32 bf16 data + 8 pad)
#define AHI 0             // A hi : 256 x 80 = 20480
#define ALO 20480         // A lo
#define BHI 40960         // B hi : 192 x 80 = 15360
#define BLO 56320         // B lo
#define BF16SZ 71680

// fp32 staging (double buffered), row stride 144 B (36 floats)
#define SSTRIDE 144
#define ASTG (256 * SSTRIDE)          // 36864
#define BSTG (192 * SSTRIDE)          // 27648
#define STG0 BF16SZ                   // 71680
#define STG1 (STG0 + ASTG + BSTG)     // 136192
#define SMEM_TOTAL (STG1 + ASTG + BSTG)   // 200704

// epilogue scratch reuses stage0 region (free after last convert)
#define SM_PSUM STG0                  // float[192][8]
#define SM_PSQ  (SM_PSUM + 6144)      // float[192][8]
#define SM_PA   (SM_PSQ + 6144)
#define SM_PB   (SM_PA + 768)
#define SM_PW   (SM_PB + 768)
#define SM_PD   (SM_PW + 768)         // float[256][2] partial row dots

// m16n8k16 bf16 HMMA, fp32 accumulate (sm_80+, assembles on compute_103)
#define MMA(d, a, b0, b1)                                                    \
    asm volatile(                                                            \
        "mma.sync.aligned.m16n8k16.row.col.f32.bf16.bf16.f32 "               \
        "{%0,%1,%2,%3}, {%4,%5,%6,%7}, {%8,%9}, {%0,%1,%2,%3};"              \
        : "+f"((d)[0]), "+f"((d)[1]), "+f"((d)[2]), "+f"((d)[3])             \
        : "r"((a)[0]), "r"((a)[1]), "r"((a)[2]), "r"((a)[3]),                \
          "r"(b0), "r"(b1))

#define LDM4(r, a)                                                           \
    asm volatile("ldmatrix.sync.aligned.m8n8.x4.shared.b16 {%0,%1,%2,%3}, [%4];" \
        : "=r"((r)[0]), "=r"((r)[1]), "=r"((r)[2]), "=r"((r)[3]) : "r"(a))

#define CPASYNC16(dst, src)                                                  \
    asm volatile("cp.async.cg.shared.global [%0], [%1], 16;"                 \
        :: "r"(dst), "l"(src) : "memory")
#define CPCOMMIT() asm volatile("cp.async.commit_group;" ::: "memory")
#define CPWAIT(n)  asm volatile("cp.async.wait_group %0;" :: "n"(n) : "memory")

static __device__ __forceinline__ unsigned smem_u32(const void* p) {
    unsigned a;
    asm("{ .reg .u64 t; cvta.to.shared.u64 t, %1; cvt.u32.u64 %0, t; }"
        : "=r"(a) : "l"(p));
    return a;
}

// 8 fp32 -> packed bf16 hi + bf16 lo (3xBF16 precision-recovery split)
static __device__ __forceinline__ void cvt8(const float4& A, const float4& B,
                                            uint4& hi, uint4& lo) {
    float f[8] = {A.x, A.y, A.z, A.w, B.x, B.y, B.z, B.w};
    unsigned h[4], l[4];
#pragma unroll
    for (int j = 0; j < 4; j++) {
        __nv_bfloat162 hp = __floats2bfloat162_rn(f[2 * j], f[2 * j + 1]);
        float r0 = f[2 * j]     - __bfloat162float(hp.x);
        float r1 = f[2 * j + 1] - __bfloat162float(hp.y);
        __nv_bfloat162 lp = __floats2bfloat162_rn(r0, r1);
        h[j] = *reinterpret_cast<unsigned*>(&hp);
        l[j] = *reinterpret_cast<unsigned*>(&lp);
    }
    hi = make_uint4(h[0], h[1], h[2], h[3]);
    lo = make_uint4(l[0], l[1], l[2], l[3]);
}

__global__ void __launch_bounds__(NTHREADS, 1)
mmlp_kernel(const float* __restrict__ x, const float* __restrict__ W1,
            const float* __restrict__ gamma, const float* __restrict__ beta,
            const float* __restrict__ W2, const float* __restrict__ b2,
            float* __restrict__ out) {
    extern __shared__ char smem[];
    const unsigned sb = smem_u32(smem);
    const int tid = threadIdx.x;
    const int lid = tid & 31;
    const int w   = tid >> 5;          // 16 warps
    const int mb  = w >> 1;            // m-block: rows [32*mb, 32*mb+32)
    const int nh  = w & 1;             // n-half: cols [96*nh, 96*nh+96)
    const int c   = blockIdx.x;
    const int g_  = lid >> 2;          // fragment group row

    // cp.async issue for chunk k into stage at byte offset stg
    auto issue_chunk = [&](int k, unsigned stg) {
        const float* xs = x + c * (size_t)FIN + k * KC;
        const float* ws = W1 + (size_t)c * FHID * FIN + k * KC;
#pragma unroll
        for (int q = 0; q < 4; q++) {              // A: 2048 16B segs
            int s = tid + q * NTHREADS;
            int row = s >> 3, seg = s & 7;
            CPASYNC16(sb + stg + row * SSTRIDE + seg * 16,
                      xs + (size_t)row * (CELLS * FIN) + seg * 4);
        }
#pragma unroll
        for (int q = 0; q < 3; q++) {              // B: 1536 16B segs
            int s = tid + q * NTHREADS;
            int row = s >> 3, seg = s & 7;
            CPASYNC16(sb + stg + ASTG + row * SSTRIDE + seg * 16,
                      ws + (size_t)row * FIN + seg * 4);
        }
    };

    // convert stage fp32 -> bf16 hi/lo buffers (each element exactly once)
    auto convert = [&](unsigned stg) {
        // A: 256 rows x 4 groups = 1024 tasks; thread t does row t>>1,
        // groups (t&1)*2 and (t&1)*2+1
        {
            int row = tid >> 1;
            int g0 = (tid & 1) * 2;
            const char* src = smem + stg + row * SSTRIDE;
            char* dhi = smem + AHI + row * ASTRIDE;
            char* dlo = smem + ALO + row * ASTRIDE;
#pragma unroll
            for (int e = 0; e < 2; e++) {
                int gg = g0 + e;
                float4 v0 = *reinterpret_cast<const float4*>(src + gg * 32);
                float4 v1 = *reinterpret_cast<const float4*>(src + gg * 32 + 16);
                uint4 hi, lo;
                cvt8(v0, v1, hi, lo);
                *reinterpret_cast<uint4*>(dhi + gg * 16) = hi;
                *reinterpret_cast<uint4*>(dlo + gg * 16) = lo;
            }
        }
        // B: 192 rows x 4 groups = 768 tasks; threads 0..383
        if (tid < 2 * FHID) {
            int row = tid >> 1;
            int g0 = (tid & 1) * 2;
            const char* src = smem + stg + ASTG + row * SSTRIDE;
            char* dhi = smem + BHI + row * ASTRIDE;
            char* dlo = smem + BLO + row * ASTRIDE;
#pragma unroll
            for (int e = 0; e < 2; e++) {
                int gg = g0 + e;
                float4 v0 = *reinterpret_cast<const float4*>(src + gg * 32);
                float4 v1 = *reinterpret_cast<const float4*>(src + gg * 32 + 16);
                uint4 hi, lo;
                cvt8(v0, v1, hi, lo);
                *reinterpret_cast<uint4*>(dhi + gg * 16) = hi;
                *reinterpret_cast<uint4*>(dlo + gg * 16) = lo;
            }
        }
    };

    // C accumulators: warp tile 32(M) x 96(N) -> 2 m16-tiles x 12 n8-tiles x 4
    float acc[2][12][4];
#pragma unroll
    for (int mt = 0; mt < 2; mt++)
#pragma unroll
        for (int nt = 0; nt < 12; nt++)
#pragma unroll
            for (int j = 0; j < 4; j++) acc[mt][nt][j] = 0.f;

    // ldmatrix per-lane base addresses (same proven mappings as R8)
    const unsigned aoff = (unsigned)((mb * 32 + (lid & 15)) * ASTRIDE +
                                     (lid >> 4) * 16);
    const unsigned boff = (unsigned)((nh * 96 + ((lid >> 4) * 8) + (lid & 7)) * ASTRIDE +
                                     ((lid >> 3) & 1) * 16);

    // ---- Prologue: stage chunks 0 and 1, convert chunk 0 ----
    issue_chunk(0, STG0); CPCOMMIT();
    issue_chunk(1, STG1); CPCOMMIT();
    CPWAIT(1);
    __syncthreads();
    convert(STG0);
    __syncthreads();

    // ---- Mainloop ----
#pragma unroll 1
    for (int i = 0; i < NCHUNK; i++) {
#pragma unroll
        for (int kk = 0; kk < 2; kk++) {
            unsigned ah[2][4], al[2][4];
            unsigned ka = aoff + kk * 32;
            LDM4(ah[0], sb + AHI + ka);
            LDM4(ah[1], sb + AHI + ka + 16 * ASTRIDE);
            LDM4(al[0], sb + ALO + ka);
            LDM4(al[1], sb + ALO + ka + 16 * ASTRIDE);
#pragma unroll
            for (int j = 0; j < 6; j++) {         // nt pairs (2j, 2j+1)
                unsigned bh[4], bl[4];
                unsigned kb = boff + j * 16 * ASTRIDE + kk * 32;
                LDM4(bh, sb + BHI + kb);
                LDM4(bl, sb + BLO + kb);
#pragma unroll
                for (int mt = 0; mt < 2; mt++) {
                    MMA(acc[mt][2 * j],     ah[mt], bh[0], bh[1]);  // hi*hi
                    MMA(acc[mt][2 * j],     ah[mt], bl[0], bl[1]);  // hi*lo
                    MMA(acc[mt][2 * j],     al[mt], bh[0], bh[1]);  // lo*hi
                    MMA(acc[mt][2 * j + 1], ah[mt], bh[2], bh[3]);
                    MMA(acc[mt][2 * j + 1], ah[mt], bl[2], bl[3]);
                    MMA(acc[mt][2 * j + 1], al[mt], bh[2], bh[3]);
                }
            }
        }
        if (i < NCHUNK - 1) {
            __syncthreads();                      // all MMA reads of bf16 done
            CPWAIT(0);                            // chunk i+1 staged
            if (i + 2 < NCHUNK) {
                issue_chunk(i + 2, (i & 1) ? STG1 : STG0);
                CPCOMMIT();
            }
            convert(((i + 1) & 1) ? STG1 : STG0);
            __syncthreads();                      // bf16 buffer ready
        }
    }

    // ---- Epilogue ----
    float* psum = reinterpret_cast<float*>(smem + SM_PSUM);
    float* psq  = reinterpret_cast<float*>(smem + SM_PSQ);
    float* pa   = reinterpret_cast<float*>(smem + SM_PA);
    float* pb   = reinterpret_cast<float*>(smem + SM_PB);
    float* pw   = reinterpret_cast<float*>(smem + SM_PW);
    float* pd   = reinterpret_cast<float*>(smem + SM_PD);

    __syncthreads();      // everyone past MMAs before stage0 region is reused

    // Per-column partial sums over this warp's 32 rows
#pragma unroll
    for (int nt = 0; nt < 12; nt++) {
        float s0 = acc[0][nt][0] + acc[0][nt][2] + acc[1][nt][0] + acc[1][nt][2];
        float s1 = acc[0][nt][1] + acc[0][nt][3] + acc[1][nt][1] + acc[1][nt][3];
        float q0 = acc[0][nt][0] * acc[0][nt][0] + acc[0][nt][2] * acc[0][nt][2] +
                   acc[1][nt][0] * acc[1][nt][0] + acc[1][nt][2] * acc[1][nt][2];
        float q1 = acc[0][nt][1] * acc[0][nt][1] + acc[0][nt][3] * acc[0][nt][3] +
                   acc[1][nt][1] * acc[1][nt][1] + acc[1][nt][3] * acc[1][nt][3];
#pragma unroll
        for (int m = 4; m <= 16; m <<= 1) {
            s0 += __shfl_xor_sync(0xFFFFFFFFu, s0, m);
            s1 += __shfl_xor_sync(0xFFFFFFFFu, s1, m);
            q0 += __shfl_xor_sync(0xFFFFFFFFu, q0, m);
            q1 += __shfl_xor_sync(0xFFFFFFFFu, q1, m);
        }
        if (lid < 4) {
            int col = nh * 96 + nt * 8 + lid * 2;
            psum[col * 8 + mb] = s0;
            psum[(col + 1) * 8 + mb] = s1;
            psq[col * 8 + mb] = q0;
            psq[(col + 1) * 8 + mb] = q1;
        }
    }
    __syncthreads();

    if (tid < FHID) {
        float s = 0.f, qq = 0.f;
#pragma unroll
        for (int j = 0; j < 8; j++) {
            s += psum[tid * 8 + j];
            qq += psq[tid * 8 + j];
        }
        float mean = s * (1.f / BATCH);
        float var = fmaf(-mean, mean, qq * (1.f / BATCH));   // biased variance
        float rstd = rsqrtf(var + 1e-5f);
        float a = gamma[(size_t)c * FHID + tid] * rstd;
        pa[tid] = a;
        pb[tid] = fmaf(-mean, a, beta[(size_t)c * FHID + tid]);
        pw[tid] = W2[(size_t)c * FHID + tid];
    }
    __syncthreads();

    // Transform + per-row partial dot over this warp's 96 columns
    float rd0 = 0.f, rd1 = 0.f, rd2 = 0.f, rd3 = 0.f;
#pragma unroll
    for (int nt = 0; nt < 12; nt++) {
        int col = nh * 96 + nt * 8 + (lid & 3) * 2;
        float a0 = pa[col], a1 = pa[col + 1];
        float b0 = pb[col], b1 = pb[col + 1];
        float w0 = pw[col], w1 = pw[col + 1];
        rd0 = fmaf(fmaxf(fmaf(a0, acc[0][nt][0], b0), 0.f), w0,
              fmaf(fmaxf(fmaf(a1, acc[0][nt][1], b1), 0.f), w1, rd0));
        rd1 = fmaf(fmaxf(fmaf(a0, acc[0][nt][2], b0), 0.f), w0,
              fmaf(fmaxf(fmaf(a1, acc[0][nt][3], b1), 0.f), w1, rd1));
        rd2 = fmaf(fmaxf(fmaf(a0, acc[1][nt][0], b0), 0.f), w0,
              fmaf(fmaxf(fmaf(a1, acc[1][nt][1], b1), 0.f), w1, rd2));
        rd3 = fmaf(fmaxf(fmaf(a0, acc[1][nt][2], b0), 0.f), w0,
              fmaf(fmaxf(fmaf(a1, acc[1][nt][3], b1), 0.f), w1, rd3));
    }
#pragma unroll
    for (int m = 1; m <= 2; m <<= 1) {
        rd0 += __shfl_xor_sync(0xFFFFFFFFu, rd0, m);
        rd1 += __shfl_xor_sync(0xFFFFFFFFu, rd1, m);
        rd2 += __shfl_xor_sync(0xFFFFFFFFu, rd2, m);
        rd3 += __shfl_xor_sync(0xFFFFFFFFu, rd3, m);
    }
    if ((lid & 3) == 0) {
        int r0 = mb * 32 + g_;
        pd[(r0)      * 2 + nh] = rd0;
        pd[(r0 + 8)  * 2 + nh] = rd1;
        pd[(r0 + 16) * 2 + nh] = rd2;
        pd[(r0 + 24) * 2 + nh] = rd3;
    }
    __syncthreads();

    if (tid < BATCH) {
        out[(size_t)tid * CELLS + c] = pd[tid * 2] + pd[tid * 2 + 1] + b2[c];
    }
}

extern "C" void kernel_launch(void* const* d_in, const int* in_sizes, int n_in,
                              void* d_out, int out_size) {
    const float* x     = (const float*)d_in[0];
    const float* W1    = (const float*)d_in[1];
    const float* gamma = (const float*)d_in[2];
    const float* beta  = (const float*)d_in[3];
    const float* W2    = (const float*)d_in[4];
    const float* b2    = (const float*)d_in[5];
    float* out = (float*)d_out;
    (void)in_sizes; (void)n_in; (void)out_size;

    cudaFuncSetAttribute(mmlp_kernel, cudaFuncAttributeMaxDynamicSharedMemorySize,
                         SMEM_TOTAL);
    mmlp_kernel<<<CELLS, NTHREADS, SMEM_TOTAL>>>(x, W1, gamma, beta, W2, b2, out);
}

// round 13
// speedup vs baseline: 1.3052x; 1.3052x over previous
#include <cuda_runtime.h>
#include <cuda_bf16.h>
#include <cstdint>

// Problem constants (fixed shapes)
#define CELLS 4096
#define BATCH 256
#define FIN   160
#define FHID  192
#define NHALF 96          // N columns per CTA (2 CTAs per cell)
#define KC    32          // K-chunk (5 chunks of 32 = 160)
#define NCHUNK 5

// bf16 operand buffers (single, per chunk): padded stride 40 bf16 (80 B)
#define ASTRIDE 80        // bytes per bf16 row (32 bf16 data + 8 pad)
#define AHI 0             // A hi : 256 x 80 = 20480
#define ALO 20480         // A lo
#define BHI 40960         // B hi : 96 x 80 = 7680
#define BLO 48640         // B lo
#define BF16SZ 56320

// fp32 staging (double buffered), row stride 144 B (36 floats)
#define SSTRIDE 144
#define ASTG (256 * SSTRIDE)          // 36864
#define BSTG (96 * SSTRIDE)           // 13824
#define STG0 BF16SZ                   // 56320
#define STG1 (STG0 + ASTG + BSTG)     // 107008
#define SMEM_TOTAL (STG1 + ASTG + BSTG)   // 157696

// epilogue scratch reuses the bf16 region (free after mainloop sync)
#define SM_PSUM 0                     // float[96][8]
#define SM_PSQ  3072                  // float[96][8]
#define SM_PA   6144                  // float[96]
#define SM_PB   6528
#define SM_PW   6912

// m16n8k16 bf16 HMMA, fp32 accumulate (sm_80+, assembles on compute_103)
#define MMA(d, a, b0, b1)                                                    \
    asm volatile(                                                            \
        "mma.sync.aligned.m16n8k16.row.col.f32.bf16.bf16.f32 "               \
        "{%0,%1,%2,%3}, {%4,%5,%6,%7}, {%8,%9}, {%0,%1,%2,%3};"              \
        : "+f"((d)[0]), "+f"((d)[1]), "+f"((d)[2]), "+f"((d)[3])             \
        : "r"((a)[0]), "r"((a)[1]), "r"((a)[2]), "r"((a)[3]),                \
          "r"(b0), "r"(b1))

#define LDM4(r, a)                                                           \
    asm volatile("ldmatrix.sync.aligned.m8n8.x4.shared.b16 {%0,%1,%2,%3}, [%4];" \
        : "=r"((r)[0]), "=r"((r)[1]), "=r"((r)[2]), "=r"((r)[3]) : "r"(a))

#define CPASYNC16(dst, src)                                                  \
    asm volatile("cp.async.cg.shared.global [%0], [%1], 16;"                 \
        :: "r"(dst), "l"(src) : "memory")
#define CPCOMMIT() asm volatile("cp.async.commit_group;" ::: "memory")
#define CPWAIT(n)  asm volatile("cp.async.wait_group %0;" :: "n"(n) : "memory")

static __device__ __forceinline__ unsigned smem_u32(const void* p) {
    unsigned a;
    asm("{ .reg .u64 t; cvta.to.shared.u64 t, %1; cvt.u32.u64 %0, t; }"
        : "=r"(a) : "l"(p));
    return a;
}

// 8 fp32 -> packed bf16 hi + bf16 lo (3xBF16 precision-recovery split)
static __device__ __forceinline__ void cvt8(const float4& A, const float4& B,
                                            uint4& hi, uint4& lo) {
    float f[8] = {A.x, A.y, A.z, A.w, B.x, B.y, B.z, B.w};
    unsigned h[4], l[4];
#pragma unroll
    for (int j = 0; j < 4; j++) {
        __nv_bfloat162 hp = __floats2bfloat162_rn(f[2 * j], f[2 * j + 1]);
        float r0 = f[2 * j]     - __bfloat162float(hp.x);
        float r1 = f[2 * j + 1] - __bfloat162float(hp.y);
        __nv_bfloat162 lp = __floats2bfloat162_rn(r0, r1);
        h[j] = *reinterpret_cast<unsigned*>(&hp);
        l[j] = *reinterpret_cast<unsigned*>(&lp);
    }
    hi = make_uint4(h[0], h[1], h[2], h[3]);
    lo = make_uint4(l[0], l[1], l[2], l[3]);
}

__global__ void zero_out_kernel(float* __restrict__ out) {
    out[(size_t)blockIdx.x * 256 + threadIdx.x] = 0.f;
}

__global__ void __launch_bounds__(256, 1)
mmlp_kernel(const float* __restrict__ x, const float* __restrict__ W1,
            const float* __restrict__ gamma, const float* __restrict__ beta,
            const float* __restrict__ W2, const float* __restrict__ b2,
            float* __restrict__ out) {
    extern __shared__ char smem[];
    const unsigned sb = smem_u32(smem);
    const int tid = threadIdx.x;
    const int lid = tid & 31;
    const int w   = tid >> 5;          // 8 warps: rows [32w, 32w+32)
    const int c   = blockIdx.x >> 1;   // cell
    const int nh  = blockIdx.x & 1;    // n-half: global cols [96nh, 96nh+96)
    const int g_  = lid >> 2;

    // cp.async issue for chunk k into stage at byte offset stg
    auto issue_chunk = [&](int k, unsigned stg) {
        const float* xs = x + c * (size_t)FIN + k * KC;
        const float* ws = W1 + ((size_t)c * FHID + nh * NHALF) * FIN + k * KC;
#pragma unroll
        for (int q = 0; q < 8; q++) {              // A: 2048 16B segs
            int s = tid + q * 256;
            int row = s >> 3, seg = s & 7;
            CPASYNC16(sb + stg + row * SSTRIDE + seg * 16,
                      xs + (size_t)row * (CELLS * FIN) + seg * 4);
        }
#pragma unroll
        for (int q = 0; q < 3; q++) {              // B: 768 16B segs
            int s = tid + q * 256;
            int row = s >> 3, seg = s & 7;
            CPASYNC16(sb + stg + ASTG + row * SSTRIDE + seg * 16,
                      ws + (size_t)row * FIN + seg * 4);
        }
    };

    // convert stage fp32 -> bf16 hi/lo buffers (each element exactly once)
    auto convert = [&](unsigned stg) {
        // A: 256 rows, thread t = row t, 4 groups of 8 floats
        {
            const char* src = smem + stg + tid * SSTRIDE;
            char* dhi = smem + AHI + tid * ASTRIDE;
            char* dlo = smem + ALO + tid * ASTRIDE;
#pragma unroll
            for (int gg = 0; gg < 4; gg++) {
                float4 v0 = *reinterpret_cast<const float4*>(src + gg * 32);
                float4 v1 = *reinterpret_cast<const float4*>(src + gg * 32 + 16);
                uint4 hi, lo;
                cvt8(v0, v1, hi, lo);
                *reinterpret_cast<uint4*>(dhi + gg * 16) = hi;
                *reinterpret_cast<uint4*>(dlo + gg * 16) = lo;
            }
        }
        // B: 96 rows x 4 groups = 384 tasks; threads 0..191 do 2 each
        if (tid < 192) {
            int row = tid >> 1;
            int g0 = (tid & 1) * 2;
            const char* src = smem + stg + ASTG + row * SSTRIDE;
            char* dhi = smem + BHI + row * ASTRIDE;
            char* dlo = smem + BLO + row * ASTRIDE;
#pragma unroll
            for (int e = 0; e < 2; e++) {
                int gg = g0 + e;
                float4 v0 = *reinterpret_cast<const float4*>(src + gg * 32);
                float4 v1 = *reinterpret_cast<const float4*>(src + gg * 32 + 16);
                uint4 hi, lo;
                cvt8(v0, v1, hi, lo);
                *reinterpret_cast<uint4*>(dhi + gg * 16) = hi;
                *reinterpret_cast<uint4*>(dlo + gg * 16) = lo;
            }
        }
    };

    // C accumulators: warp tile 32(M) x 96(N) -> 2 m16-tiles x 12 n8-tiles x 4
    float acc[2][12][4];
#pragma unroll
    for (int mt = 0; mt < 2; mt++)
#pragma unroll
        for (int nt = 0; nt < 12; nt++)
#pragma unroll
            for (int j = 0; j < 4; j++) acc[mt][nt][j] = 0.f;

    // ldmatrix per-lane base addresses (proven mappings)
    const unsigned aoff = (unsigned)((w * 32 + (lid & 15)) * ASTRIDE +
                                     (lid >> 4) * 16);
    const unsigned boff = (unsigned)((((lid >> 4) * 8) + (lid & 7)) * ASTRIDE +
                                     ((lid >> 3) & 1) * 16);

    // ---- Prologue: stage chunks 0 and 1, convert chunk 0 ----
    issue_chunk(0, STG0); CPCOMMIT();
    issue_chunk(1, STG1); CPCOMMIT();
    CPWAIT(1);
    __syncthreads();
    convert(STG0);
    __syncthreads();

    // ---- Mainloop ----
#pragma unroll 1
    for (int i = 0; i < NCHUNK; i++) {
#pragma unroll
        for (int kk = 0; kk < 2; kk++) {
            unsigned ah[2][4], al[2][4];
            unsigned ka = aoff + kk * 32;
            LDM4(ah[0], sb + AHI + ka);
            LDM4(ah[1], sb + AHI + ka + 16 * ASTRIDE);
            LDM4(al[0], sb + ALO + ka);
            LDM4(al[1], sb + ALO + ka + 16 * ASTRIDE);
#pragma unroll
            for (int j = 0; j < 6; j++) {         // nt pairs (2j, 2j+1)
                unsigned bh[4], bl[4];
                unsigned kb = boff + j * 16 * ASTRIDE + kk * 32;
                LDM4(bh, sb + BHI + kb);
                LDM4(bl, sb + BLO + kb);
#pragma unroll
                for (int mt = 0; mt < 2; mt++) {
                    MMA(acc[mt][2 * j],     ah[mt], bh[0], bh[1]);  // hi*hi
                    MMA(acc[mt][2 * j],     ah[mt], bl[0], bl[1]);  // hi*lo
                    MMA(acc[mt][2 * j],     al[mt], bh[0], bh[1]);  // lo*hi
                    MMA(acc[mt][2 * j + 1], ah[mt], bh[2], bh[3]);
                    MMA(acc[mt][2 * j + 1], ah[mt], bl[2], bl[3]);
                    MMA(acc[mt][2 * j + 1], al[mt], bh[2], bh[3]);
                }
            }
        }
        if (i < NCHUNK - 1) {
            __syncthreads();                      // all MMA reads of bf16 done
            CPWAIT(0);                            // chunk i+1 staged
            if (i + 2 < NCHUNK) {
                issue_chunk(i + 2, (i & 1) ? STG1 : STG0);
                CPCOMMIT();
            }
            convert(((i + 1) & 1) ? STG1 : STG0);
            __syncthreads();                      // bf16 buffer ready
        }
    }

    // ---- Epilogue (local to this CTA's 96 columns) ----
    float* psum = reinterpret_cast<float*>(smem + SM_PSUM);
    float* psq  = reinterpret_cast<float*>(smem + SM_PSQ);
    float* pa   = reinterpret_cast<float*>(smem + SM_PA);
    float* pb   = reinterpret_cast<float*>(smem + SM_PB);
    float* pw   = reinterpret_cast<float*>(smem + SM_PW);

    __syncthreads();      // everyone past MMAs before bf16 region is reused

    // Per-column partial sums over this warp's 32 rows
#pragma unroll
    for (int nt = 0; nt < 12; nt++) {
        float s0 = acc[0][nt][0] + acc[0][nt][2] + acc[1][nt][0] + acc[1][nt][2];
        float s1 = acc[0][nt][1] + acc[0][nt][3] + acc[1][nt][1] + acc[1][nt][3];
        float q0 = acc[0][nt][0] * acc[0][nt][0] + acc[0][nt][2] * acc[0][nt][2] +
                   acc[1][nt][0] * acc[1][nt][0] + acc[1][nt][2] * acc[1][nt][2];
        float q1 = acc[0][nt][1] * acc[0][nt][1] + acc[0][nt][3] * acc[0][nt][3] +
                   acc[1][nt][1] * acc[1][nt][1] + acc[1][nt][3] * acc[1][nt][3];
#pragma unroll
        for (int m = 4; m <= 16; m <<= 1) {
            s0 += __shfl_xor_sync(0xFFFFFFFFu, s0, m);
            s1 += __shfl_xor_sync(0xFFFFFFFFu, s1, m);
            q0 += __shfl_xor_sync(0xFFFFFFFFu, q0, m);
            q1 += __shfl_xor_sync(0xFFFFFFFFu, q1, m);
        }
        if (lid < 4) {
            int col = nt * 8 + lid * 2;           // local column (0..95)
            psum[col * 8 + w] = s0;
            psum[(col + 1) * 8 + w] = s1;
            psq[col * 8 + w] = q0;
            psq[(col + 1) * 8 + w] = q1;
        }
    }
    __syncthreads();

    if (tid < NHALF) {
        float s = 0.f, qq = 0.f;
#pragma unroll
        for (int j = 0; j < 8; j++) {
            s += psum[tid * 8 + j];
            qq += psq[tid * 8 + j];
        }
        float mean = s * (1.f / BATCH);
        float var = fmaf(-mean, mean, qq * (1.f / BATCH));   // biased variance
        float rstd = rsqrtf(var + 1e-5f);
        size_t gcol = (size_t)c * FHID + nh * NHALF + tid;
        float a = gamma[gcol] * rstd;
        pa[tid] = a;
        pb[tid] = fmaf(-mean, a, beta[gcol]);
        pw[tid] = W2[gcol];
    }
    __syncthreads();

    // Transform + per-row partial dot over this CTA's 96 columns
    float rd0 = 0.f, rd1 = 0.f, rd2 = 0.f, rd3 = 0.f;
#pragma unroll
    for (int nt = 0; nt < 12; nt++) {
        int col = nt * 8 + (lid & 3) * 2;
        float a0 = pa[col], a1 = pa[col + 1];
        float b0 = pb[col], b1 = pb[col + 1];
        float w0 = pw[col], w1 = pw[col + 1];
        rd0 = fmaf(fmaxf(fmaf(a0, acc[0][nt][0], b0), 0.f), w0,
              fmaf(fmaxf(fmaf(a1, acc[0][nt][1], b1), 0.f), w1, rd0));
        rd1 = fmaf(fmaxf(fmaf(a0, acc[0][nt][2], b0), 0.f), w0,
              fmaf(fmaxf(fmaf(a1, acc[0][nt][3], b1), 0.f), w1, rd1));
        rd2 = fmaf(fmaxf(fmaf(a0, acc[1][nt][0], b0), 0.f), w0,
              fmaf(fmaxf(fmaf(a1, acc[1][nt][1], b1), 0.f), w1, rd2));
        rd3 = fmaf(fmaxf(fmaf(a0, acc[1][nt][2], b0), 0.f), w0,
              fmaf(fmaxf(fmaf(a1, acc[1][nt][3], b1), 0.f), w1, rd3));
    }
#pragma unroll
    for (int m = 1; m <= 2; m <<= 1) {
        rd0 += __shfl_xor_sync(0xFFFFFFFFu, rd0, m);
        rd1 += __shfl_xor_sync(0xFFFFFFFFu, rd1, m);
        rd2 += __shfl_xor_sync(0xFFFFFFFFu, rd2, m);
        rd3 += __shfl_xor_sync(0xFFFFFFFFu, rd3, m);
    }
    if ((lid & 3) == 0) {
        // Combine the two N-halves: fp32 atomicAdd of exactly two values is
        // order-independent (a+b == b+a), so the result is deterministic.
        float add = (nh == 0) ? b2[c] : 0.f;
        int r0 = w * 32 + g_;
        atomicAdd(&out[(size_t)(r0)      * CELLS + c], rd0 + add);
        atomicAdd(&out[(size_t)(r0 + 8)  * CELLS + c], rd1 + add);
        atomicAdd(&out[(size_t)(r0 + 16) * CELLS + c], rd2 + add);
        atomicAdd(&out[(size_t)(r0 + 24) * CELLS + c], rd3 + add);
    }
}

extern "C" void kernel_launch(void* const* d_in, const int* in_sizes, int n_in,
                              void* d_out, int out_size) {
    const float* x     = (const float*)d_in[0];
    const float* W1    = (const float*)d_in[1];
    const float* gamma = (const float*)d_in[2];
    const float* beta  = (const float*)d_in[3];
    const float* W2    = (const float*)d_in[4];
    const float* b2    = (const float*)d_in[5];
    float* out = (float*)d_out;
    (void)in_sizes; (void)n_in; (void)out_size;

    zero_out_kernel<<<CELLS, 256>>>(out);   // out = BATCH*CELLS = 4096*256

    cudaFuncSetAttribute(mmlp_kernel, cudaFuncAttributeMaxDynamicSharedMemorySize,
                         SMEM_TOTAL);
    mmlp_kernel<<<CELLS * 2, 256, SMEM_TOTAL>>>(x, W1, gamma, beta, W2, b2, out);
}

// round 15
// speedup vs baseline: 1.6507x; 1.2648x over previous
#include <cuda_runtime.h>
#include <cuda_bf16.h>
#include <cstdint>

// Problem constants (fixed shapes)
#define CELLS 4096
#define BATCH 256
#define FIN   160
#define FHID  192
#define KC    32          // K-chunk (5 chunks of 32 = 160)
#define NCHUNK 5

// bf16 operand buffers, DOUBLE buffered. Padded stride 40 bf16 (80 B):
// conflict-free for ldmatrix 8-row phases and convert STS.
#define ASTRIDE 80        // bytes per bf16 row (32 bf16 data + 8 pad)
#define AHI 0             // A hi : 256 x 80 = 20480   (offsets within a buffer)
#define ALO 20480         // A lo
#define BHI 40960         // B hi : 192 x 80 = 15360
#define BLO 56320         // B lo
#define BFSZ 71680
#define BF0 0
#define BF1 BFSZ

// fp32 staging, SINGLE buffer, row stride 144 B (36 floats)
#define SSTRIDE 144
#define STG  (2 * BFSZ)                 // 143360 : A staging (256 rows)
#define STGB (STG + 256 * SSTRIDE)      // 180224 : B staging (192 rows)
#define SMEM_TOTAL (STGB + 192 * SSTRIDE)   // 207872

// epilogue scratch reuses BF0 (free after the final chunk's barrier)
#define SM_PSUM 0                       // float[192][8]
#define SM_PSQ  6144                    // float[192][8]
#define SM_PA   12288                   // float[192]
#define SM_PB   (SM_PA + 768)
#define SM_PW   (SM_PB + 768)

// m16n8k16 bf16 HMMA, fp32 accumulate (sm_80+, assembles on compute_103)
#define MMA(d, a, b0, b1)                                                    \
    asm volatile(                                                            \
        "mma.sync.aligned.m16n8k16.row.col.f32.bf16.bf16.f32 "               \
        "{%0,%1,%2,%3}, {%4,%5,%6,%7}, {%8,%9}, {%0,%1,%2,%3};"              \
        : "+f"((d)[0]), "+f"((d)[1]), "+f"((d)[2]), "+f"((d)[3])             \
        : "r"((a)[0]), "r"((a)[1]), "r"((a)[2]), "r"((a)[3]),                \
          "r"(b0), "r"(b1))

#define LDM4(r, a)                                                           \
    asm volatile("ldmatrix.sync.aligned.m8n8.x4.shared.b16 {%0,%1,%2,%3}, [%4];" \
        : "=r"((r)[0]), "=r"((r)[1]), "=r"((r)[2]), "=r"((r)[3]) : "r"(a))

#define CPASYNC16(dst, src)                                                  \
    asm volatile("cp.async.cg.shared.global [%0], [%1], 16;"                 \
        :: "r"(dst), "l"(src) : "memory")
#define CPCOMMIT() asm volatile("cp.async.commit_group;" ::: "memory")
#define CPWAIT(n)  asm volatile("cp.async.wait_group %0;" :: "n"(n) : "memory")

static __device__ __forceinline__ unsigned smem_u32(const void* p) {
    unsigned a;
    asm("{ .reg .u64 t; cvta.to.shared.u64 t, %1; cvt.u32.u64 %0, t; }"
        : "=r"(a) : "l"(p));
    return a;
}

// 8 fp32 -> packed bf16 hi + bf16 lo (3xBF16 precision-recovery split)
static __device__ __forceinline__ void cvt8(const float4& A, const float4& B,
                                            uint4& hi, uint4& lo) {
    float f[8] = {A.x, A.y, A.z, A.w, B.x, B.y, B.z, B.w};
    unsigned h[4], l[4];
#pragma unroll
    for (int j = 0; j < 4; j++) {
        __nv_bfloat162 hp = __floats2bfloat162_rn(f[2 * j], f[2 * j + 1]);
        float r0 = f[2 * j]     - __bfloat162float(hp.x);
        float r1 = f[2 * j + 1] - __bfloat162float(hp.y);
        __nv_bfloat162 lp = __floats2bfloat162_rn(r0, r1);
        h[j] = *reinterpret_cast<unsigned*>(&hp);
        l[j] = *reinterpret_cast<unsigned*>(&lp);
    }
    hi = make_uint4(h[0], h[1], h[2], h[3]);
    lo = make_uint4(l[0], l[1], l[2], l[3]);
}

__global__ void __launch_bounds__(256, 1)
mmlp_kernel(const float* __restrict__ x, const float* __restrict__ W1,
            const float* __restrict__ gamma, const float* __restrict__ beta,
            const float* __restrict__ W2, const float* __restrict__ b2,
            float* __restrict__ out) {
    extern __shared__ char smem[];
    const unsigned sb = smem_u32(smem);
    const int tid = threadIdx.x;
    const int lid = tid & 31;
    const int w   = tid >> 5;          // warp id: owns batch rows [32w, 32w+32)
    const int c   = blockIdx.x;
    const int g_  = lid >> 2;

    // cp.async issue for chunk k into the single fp32 staging buffer
    auto issue_chunk = [&](int k) {
        const float* xs = x + c * (size_t)FIN + k * KC;
        const float* ws = W1 + (size_t)c * FHID * FIN + k * KC;
#pragma unroll
        for (int q = 0; q < 8; q++) {              // A: 2048 16B segs
            int s = tid + q * 256;
            int row = s >> 3, seg = s & 7;
            CPASYNC16(sb + STG + row * SSTRIDE + seg * 16,
                      xs + (size_t)row * (CELLS * FIN) + seg * 4);
        }
#pragma unroll
        for (int q = 0; q < 6; q++) {              // B: 1536 16B segs
            int s = tid + q * 256;
            int row = s >> 3, seg = s & 7;
            CPASYNC16(sb + STGB + row * SSTRIDE + seg * 16,
                      ws + (size_t)row * FIN + seg * 4);
        }
    };

    // One convert micro-task (p in [0,7)): fp32 staging -> bf16 buffer nb.
    // p<4: A row tid, group p.  p>=4: B task (p-4)*256+tid.
    auto ctask = [&](int p, unsigned nb) {
        if (p < 4) {
            const char* src = smem + STG + tid * SSTRIDE + p * 32;
            float4 v0 = *reinterpret_cast<const float4*>(src);
            float4 v1 = *reinterpret_cast<const float4*>(src + 16);
            uint4 hi, lo;
            cvt8(v0, v1, hi, lo);
            char* d = smem + nb;
            *reinterpret_cast<uint4*>(d + AHI + tid * ASTRIDE + p * 16) = hi;
            *reinterpret_cast<uint4*>(d + ALO + tid * ASTRIDE + p * 16) = lo;
        } else {
            int bt = (p - 4) * 256 + tid;          // 0..767
            int row = bt >> 2, gg = bt & 3;
            const char* src = smem + STGB + row * SSTRIDE + gg * 32;
            float4 v0 = *reinterpret_cast<const float4*>(src);
            float4 v1 = *reinterpret_cast<const float4*>(src + 16);
            uint4 hi, lo;
            cvt8(v0, v1, hi, lo);
            char* d = smem + nb;
            *reinterpret_cast<uint4*>(d + BHI + row * ASTRIDE + gg * 16) = hi;
            *reinterpret_cast<uint4*>(d + BLO + row * ASTRIDE + gg * 16) = lo;
        }
    };

    // C accumulators: warp tile 32(M) x 192(N) -> 2 m16-tiles x 24 n8-tiles x 4
    float acc[2][24][4];
#pragma unroll
    for (int mt = 0; mt < 2; mt++)
#pragma unroll
        for (int nt = 0; nt < 24; nt++)
#pragma unroll
            for (int j = 0; j < 4; j++) acc[mt][nt][j] = 0.f;

    // ldmatrix per-lane base addresses (proven mappings)
    const unsigned aoff = (unsigned)((w * 32 + (lid & 15)) * ASTRIDE +
                                     (lid >> 4) * 16);
    const unsigned boff = (unsigned)((((lid >> 4) * 8) + (lid & 7)) * ASTRIDE +
                                     ((lid >> 3) & 1) * 16);

    // ---- Prologue: stage + convert chunk 0 (serial, once), then issue 1 ----
    issue_chunk(0); CPCOMMIT();
    CPWAIT(0);
    __syncthreads();
#pragma unroll
    for (int p = 0; p < 7; p++) ctask(p, BF0);
    __syncthreads();                   // bf16[0] visible; staging free
    issue_chunk(1); CPCOMMIT();

    // ---- Mainloop: MMA(chunk i) with convert(chunk i+1) interleaved ----
#pragma unroll 1
    for (int i = 0; i < NCHUNK; i++) {
        const unsigned cb = sb + ((i & 1) ? BF1 : BF0);  // current bf16 (abs)
        const unsigned nb = (i & 1) ? BF0 : BF1;         // next bf16 (offset)
        const bool hn = (i + 1 < NCHUNK);
        unsigned ah[2][4], al[2][4];
#pragma unroll
        for (int jj = 0; jj < 24; jj++) {
            const int kk = jj / 12;
            const int j = jj % 12;
            if (j == 0) {              // (re)load A fragments for this k-step
                unsigned ka = cb + AHI + aoff + kk * 32;
                LDM4(ah[0], ka);
                LDM4(ah[1], ka + 16 * ASTRIDE);
                LDM4(al[0], ka + (ALO - AHI));
                LDM4(al[1], ka + (ALO - AHI) + 16 * ASTRIDE);
            }
            unsigned kb = cb + BHI + boff + j * 16 * ASTRIDE + kk * 32;
            unsigned bh[4], bl[4];
            LDM4(bh, kb);
            LDM4(bl, kb + (BLO - BHI));
            // term-major order: same-acc RAW distance 4
            MMA(acc[0][2 * j],     ah[0], bh[0], bh[1]);   // hi*hi
            MMA(acc[1][2 * j],     ah[1], bh[0], bh[1]);
            MMA(acc[0][2 * j + 1], ah[0], bh[2], bh[3]);
            MMA(acc[1][2 * j + 1], ah[1], bh[2], bh[3]);
            MMA(acc[0][2 * j],     ah[0], bl[0], bl[1]);   // hi*lo
            MMA(acc[1][2 * j],     ah[1], bl[0], bl[1]);
            MMA(acc[0][2 * j + 1], ah[0], bl[2], bl[3]);
            MMA(acc[1][2 * j + 1], ah[1], bl[2], bl[3]);
            MMA(acc[0][2 * j],     al[0], bh[0], bh[1]);   // lo*hi
            MMA(acc[1][2 * j],     al[1], bh[0], bh[1]);
            MMA(acc[0][2 * j + 1], al[0], bh[2], bh[3]);
            MMA(acc[1][2 * j + 1], al[1], bh[2], bh[3]);
            // interleaved convert of next chunk (7 micro-tasks, jj 13..19).
            // CPWAIT orders only this thread's own cp.async ops; the barrier
            // publishes ALL threads' staged data CTA-wide before any convert
            // reads it (this was the R13 race).
            if (hn && jj >= 13 && jj <= 19) {
                if (jj == 13) {
                    CPWAIT(0);                     // own copies complete
                    __syncthreads();               // everyone's copies visible
                }
                ctask(jj - 13, nb);
            }
        }
        __syncthreads();               // bf16[next] complete; staging free
        if (i + 2 < NCHUNK) { issue_chunk(i + 2); CPCOMMIT(); }
    }

    // ---- Epilogue: BN stats + folded BN + relu + W2 dot, all in regs ----
    float* psum = reinterpret_cast<float*>(smem + SM_PSUM);
    float* psq  = reinterpret_cast<float*>(smem + SM_PSQ);
    float* pa   = reinterpret_cast<float*>(smem + SM_PA);
    float* pb   = reinterpret_cast<float*>(smem + SM_PB);
    float* pw   = reinterpret_cast<float*>(smem + SM_PW);

    // Per-column partial sums over this warp's 32 rows
#pragma unroll
    for (int nt = 0; nt < 24; nt++) {
        float s0 = acc[0][nt][0] + acc[0][nt][2] + acc[1][nt][0] + acc[1][nt][2];
        float s1 = acc[0][nt][1] + acc[0][nt][3] + acc[1][nt][1] + acc[1][nt][3];
        float q0 = acc[0][nt][0] * acc[0][nt][0] + acc[0][nt][2] * acc[0][nt][2] +
                   acc[1][nt][0] * acc[1][nt][0] + acc[1][nt][2] * acc[1][nt][2];
        float q1 = acc[0][nt][1] * acc[0][nt][1] + acc[0][nt][3] * acc[0][nt][3] +
                   acc[1][nt][1] * acc[1][nt][1] + acc[1][nt][3] * acc[1][nt][3];
#pragma unroll
        for (int m = 4; m <= 16; m <<= 1) {
            s0 += __shfl_xor_sync(0xFFFFFFFFu, s0, m);
            s1 += __shfl_xor_sync(0xFFFFFFFFu, s1, m);
            q0 += __shfl_xor_sync(0xFFFFFFFFu, q0, m);
            q1 += __shfl_xor_sync(0xFFFFFFFFu, q1, m);
        }
        if (lid < 4) {
            int col = nt * 8 + lid * 2;
            psum[col * 8 + w] = s0;
            psum[(col + 1) * 8 + w] = s1;
            psq[col * 8 + w] = q0;
            psq[(col + 1) * 8 + w] = q1;
        }
    }
    __syncthreads();

    if (tid < FHID) {
        float s = 0.f, qq = 0.f;
#pragma unroll
        for (int j = 0; j < 8; j++) {
            s += psum[tid * 8 + j];
            qq += psq[tid * 8 + j];
        }
        float mean = s * (1.f / BATCH);
        float var = fmaf(-mean, mean, qq * (1.f / BATCH));   // biased variance
        float rstd = rsqrtf(var + 1e-5f);
        float a = gamma[(size_t)c * FHID + tid] * rstd;
        pa[tid] = a;
        pb[tid] = fmaf(-mean, a, beta[(size_t)c * FHID + tid]);
        pw[tid] = W2[(size_t)c * FHID + tid];
    }
    __syncthreads();

    // Transform + per-row dot: rows (w*32 + mt*16 + g_, +8)
    float rd0 = 0.f, rd1 = 0.f, rd2 = 0.f, rd3 = 0.f;
#pragma unroll
    for (int nt = 0; nt < 24; nt++) {
        int col = nt * 8 + (lid & 3) * 2;
        float a0 = pa[col], a1 = pa[col + 1];
        float b0 = pb[col], b1 = pb[col + 1];
        float w0 = pw[col], w1 = pw[col + 1];
        rd0 = fmaf(fmaxf(fmaf(a0, acc[0][nt][0], b0), 0.f), w0,
              fmaf(fmaxf(fmaf(a1, acc[0][nt][1], b1), 0.f), w1, rd0));
        rd1 = fmaf(fmaxf(fmaf(a0, acc[0][nt][2], b0), 0.f), w0,
              fmaf(fmaxf(fmaf(a1, acc[0][nt][3], b1), 0.f), w1, rd1));
        rd2 = fmaf(fmaxf(fmaf(a0, acc[1][nt][0], b0), 0.f), w0,
              fmaf(fmaxf(fmaf(a1, acc[1][nt][1], b1), 0.f), w1, rd2));
        rd3 = fmaf(fmaxf(fmaf(a0, acc[1][nt][2], b0), 0.f), w0,
              fmaf(fmaxf(fmaf(a1, acc[1][nt][3], b1), 0.f), w1, rd3));
    }
#pragma unroll
    for (int m = 1; m <= 2; m <<= 1) {
        rd0 += __shfl_xor_sync(0xFFFFFFFFu, rd0, m);
        rd1 += __shfl_xor_sync(0xFFFFFFFFu, rd1, m);
        rd2 += __shfl_xor_sync(0xFFFFFFFFu, rd2, m);
        rd3 += __shfl_xor_sync(0xFFFFFFFFu, rd3, m);
    }
    if ((lid & 3) == 0) {
        float b2c = b2[c];
        int r0 = w * 32 + g_;
        out[(size_t)(r0)      * CELLS + c] = rd0 + b2c;
        out[(size_t)(r0 + 8)  * CELLS + c] = rd1 + b2c;
        out[(size_t)(r0 + 16) * CELLS + c] = rd2 + b2c;
        out[(size_t)(r0 + 24) * CELLS + c] = rd3 + b2c;
    }
}

extern "C" void kernel_launch(void* const* d_in, const int* in_sizes, int n_in,
                              void* d_out, int out_size) {
    const float* x     = (const float*)d_in[0];
    const float* W1    = (const float*)d_in[1];
    const float* gamma = (const float*)d_in[2];
    const float* beta  = (const float*)d_in[3];
    const float* W2    = (const float*)d_in[4];
    const float* b2    = (const float*)d_in[5];
    float* out = (float*)d_out;
    (void)in_sizes; (void)n_in; (void)out_size;

    cudaFuncSetAttribute(mmlp_kernel, cudaFuncAttributeMaxDynamicSharedMemorySize,
                         SMEM_TOTAL);
    mmlp_kernel<<<CELLS, 256, SMEM_TOTAL>>>(x, W1, gamma, beta, W2, b2, out);
}

// round 16
// speedup vs baseline: 1.8874x; 1.1434x over previous
#include <cuda_runtime.h>
#include <cuda_bf16.h>
#include <cstdint>

// Problem constants (fixed shapes)
#define CELLS 4096
#define BATCH 256
#define FIN   160
#define FHID  192
#define KC    32          // K-chunk (5 chunks of 32 = 160); 4 k8-steps each
#define NCHUNK 5

// Unified fp32 operand buffers (staged by cp.async, tf32-rounded in place,
// consumed by ldmatrix). Double buffered. Row stride 144 B (36 floats:
// 32 data + 4 pad) -> conflict-free for ldmatrix phases (banks 4r..4r+3)
// and for the float4 convert pass.
#define SSTRIDE 144
#define ABASE 0                          // A: 256 rows
#define BBASE (256 * SSTRIDE)            // 36864 : B: 192 rows
#define BUFSZ (BBASE + 192 * SSTRIDE)    // 64512
#define SMEM_TOTAL (2 * BUFSZ)           // 129024

// epilogue scratch reuses buffer 0 (after the post-mainloop barrier)
#define SM_PSUM 0                        // float[192][8]
#define SM_PSQ  6144                     // float[192][8]
#define SM_PA   12288                    // float[192]
#define SM_PB   (SM_PA + 768)
#define SM_PW   (SM_PB + 768)

// m16n8k8 tf32 MMA, fp32 accumulate (sm_80+, assembles on compute_103)
#define MMA(d, a, b0, b1)                                                    \
    asm volatile(                                                            \
        "mma.sync.aligned.m16n8k8.row.col.f32.tf32.tf32.f32 "                \
        "{%0,%1,%2,%3}, {%4,%5,%6,%7}, {%8,%9}, {%0,%1,%2,%3};"              \
        : "+f"((d)[0]), "+f"((d)[1]), "+f"((d)[2]), "+f"((d)[3])             \
        : "r"((a)[0]), "r"((a)[1]), "r"((a)[2]), "r"((a)[3]),                \
          "r"(b0), "r"(b1))

#define LDM4(r, a)                                                           \
    asm volatile("ldmatrix.sync.aligned.m8n8.x4.shared.b16 {%0,%1,%2,%3}, [%4];" \
        : "=r"((r)[0]), "=r"((r)[1]), "=r"((r)[2]), "=r"((r)[3]) : "r"(a))

#define CPASYNC16(dst, src)                                                  \
    asm volatile("cp.async.cg.shared.global [%0], [%1], 16;"                 \
        :: "r"(dst), "l"(src) : "memory")
#define CPCOMMIT() asm volatile("cp.async.commit_group;" ::: "memory")
#define CPWAIT(n)  asm volatile("cp.async.wait_group %0;" :: "n"(n) : "memory")

static __device__ __forceinline__ unsigned smem_u32(const void* p) {
    unsigned a;
    asm("{ .reg .u64 t; cvta.to.shared.u64 t, %1; cvt.u32.u64 %0, t; }"
        : "=r"(a) : "l"(p));
    return a;
}

static __device__ __forceinline__ unsigned f2tf32(float x) {
    unsigned u;
    asm("cvt.rna.tf32.f32 %0, %1;" : "=r"(u) : "f"(x));
    return u;
}

__global__ void __launch_bounds__(256, 1)
mmlp_kernel(const float* __restrict__ x, const float* __restrict__ W1,
            const float* __restrict__ gamma, const float* __restrict__ beta,
            const float* __restrict__ W2, const float* __restrict__ b2,
            float* __restrict__ out) {
    extern __shared__ char smem[];
    const unsigned sb = smem_u32(smem);
    const int tid = threadIdx.x;
    const int lid = tid & 31;
    const int w   = tid >> 5;          // warp id: owns batch rows [32w, 32w+32)
    const int c   = blockIdx.x;
    const int g_  = lid >> 2;

    // cp.async issue for chunk k into buffer (k & 1)
    auto issue_chunk = [&](int k) {
        const unsigned bb = sb + (unsigned)(k & 1) * BUFSZ;
        const float* xs = x + c * (size_t)FIN + k * KC;
        const float* ws = W1 + (size_t)c * FHID * FIN + k * KC;
#pragma unroll
        for (int q = 0; q < 8; q++) {              // A: 2048 16B segs
            int s = tid + q * 256;
            int row = s >> 3, seg = s & 7;
            CPASYNC16(bb + ABASE + row * SSTRIDE + seg * 16,
                      xs + (size_t)row * (CELLS * FIN) + seg * 4);
        }
#pragma unroll
        for (int q = 0; q < 6; q++) {              // B: 1536 16B segs
            int s = tid + q * 256;
            int row = s >> 3, seg = s & 7;
            CPASYNC16(bb + BBASE + row * SSTRIDE + seg * 16,
                      ws + (size_t)row * FIN + seg * 4);
        }
    };

    // One convert micro-task (p in [0,7)): tf32-round (RNA) two float4s of
    // buffer `bufofs` in place. 3584 float4 tasks total / 256 thr = 14 each.
    auto ctask = [&](int p, unsigned bufofs) {
#pragma unroll
        for (int e = 0; e < 2; e++) {
            int f = p * 512 + e * 256 + tid;       // 0..3583
            unsigned addr;
            if (f < 2048)  addr = bufofs + ABASE + (f >> 3) * SSTRIDE + (f & 7) * 16;
            else { int fb = f - 2048;
                   addr = bufofs + BBASE + (fb >> 3) * SSTRIDE + (fb & 7) * 16; }
            float4 v = *reinterpret_cast<const float4*>(smem + addr);
            uint4 u = make_uint4(f2tf32(v.x), f2tf32(v.y), f2tf32(v.z), f2tf32(v.w));
            *reinterpret_cast<uint4*>(smem + addr) = u;
        }
    };

    // C accumulators: warp tile 32(M) x 192(N) -> 2 m16-tiles x 24 n8-tiles x 4
    float acc[2][24][4];
#pragma unroll
    for (int mt = 0; mt < 2; mt++)
#pragma unroll
        for (int nt = 0; nt < 24; nt++)
#pragma unroll
            for (int j = 0; j < 4; j++) acc[mt][nt][j] = 0.f;

    // ldmatrix lane addressing for tf32 fragments (b16-pair trick):
    // A x4 matrices: {rows 0-7,k0-3}{rows 8-15,k0-3}{rows 0-7,k4-7}{rows 8-15,k4-7}
    const int arow = (lid & 7) + ((lid >> 3) & 1) * 8;
    const unsigned akoff = (unsigned)(((lid >> 4) & 1) * 16);
    // B x4 matrices: {nt 2j,k0-3}{nt 2j,k4-7}{nt 2j+1,k0-3}{nt 2j+1,k4-7}
    const int brow = ((lid >> 4) & 1) * 8 + (lid & 7);
    const unsigned bkoff = (unsigned)(((lid >> 3) & 1) * 16);

    // ---- Prologue: stage + round chunk 0 (serial, once), then issue 1 ----
    issue_chunk(0); CPCOMMIT();
    CPWAIT(0);
    __syncthreads();
#pragma unroll
    for (int p = 0; p < 7; p++) ctask(p, 0);
    __syncthreads();                   // buf0 tf32-ready; buf1 free
    issue_chunk(1); CPCOMMIT();

    // ---- Mainloop: MMA(chunk i, buf i&1) + convert(chunk i+1) woven in ----
#pragma unroll 1
    for (int i = 0; i < NCHUNK; i++) {
        const unsigned cb = sb + (unsigned)(i & 1) * BUFSZ;
        const unsigned nbo = (unsigned)((i + 1) & 1) * BUFSZ;   // smem offset
        const bool hn = (i + 1 < NCHUNK);
#pragma unroll
        for (int ks = 0; ks < 4; ks++) {           // k8 steps within chunk
            unsigned a[2][4];
            unsigned ka = cb + ABASE + (unsigned)((w * 32 + arow) * SSTRIDE) +
                          akoff + ks * 32;
            LDM4(a[0], ka);
            LDM4(a[1], ka + 16 * SSTRIDE);
#pragma unroll
            for (int jp = 0; jp < 12; jp++) {      // nt pairs (2jp, 2jp+1)
                unsigned b[4];
                unsigned kb = cb + BBASE +
                              (unsigned)((jp * 16 + brow) * SSTRIDE) +
                              bkoff + ks * 32;
                LDM4(b, kb);
                MMA(acc[0][2 * jp],     a[0], b[0], b[1]);
                MMA(acc[1][2 * jp],     a[1], b[0], b[1]);
                MMA(acc[0][2 * jp + 1], a[0], b[2], b[3]);
                MMA(acc[1][2 * jp + 1], a[1], b[2], b[3]);
                // interleaved tf32 rounding of next chunk (7 micro-tasks).
                // CPWAIT orders only this thread's cp.async; the barrier
                // publishes all threads' staged data before converts read it.
                const int jj = ks * 12 + jp;
                if (hn && jj >= 26 && jj <= 32) {
                    if (jj == 26) {
                        CPWAIT(0);                 // own copies complete
                        __syncthreads();           // everyone's copies visible
                    }
                    ctask(jj - 26, nbo);
                }
            }
        }
        __syncthreads();               // next buffer tf32-ready / reads done
        if (i + 2 < NCHUNK) { issue_chunk(i + 2); CPCOMMIT(); }
    }
    __syncthreads();   // all MMA reads of buf0 done before scratch reuse

    // ---- Epilogue: BN stats + folded BN + relu + W2 dot, all in regs ----
    float* psum = reinterpret_cast<float*>(smem + SM_PSUM);
    float* psq  = reinterpret_cast<float*>(smem + SM_PSQ);
    float* pa   = reinterpret_cast<float*>(smem + SM_PA);
    float* pb   = reinterpret_cast<float*>(smem + SM_PB);
    float* pw   = reinterpret_cast<float*>(smem + SM_PW);

    // Per-column partial sums over this warp's 32 rows
#pragma unroll
    for (int nt = 0; nt < 24; nt++) {
        float s0 = acc[0][nt][0] + acc[0][nt][2] + acc[1][nt][0] + acc[1][nt][2];
        float s1 = acc[0][nt][1] + acc[0][nt][3] + acc[1][nt][1] + acc[1][nt][3];
        float q0 = acc[0][nt][0] * acc[0][nt][0] + acc[0][nt][2] * acc[0][nt][2] +
                   acc[1][nt][0] * acc[1][nt][0] + acc[1][nt][2] * acc[1][nt][2];
        float q1 = acc[0][nt][1] * acc[0][nt][1] + acc[0][nt][3] * acc[0][nt][3] +
                   acc[1][nt][1] * acc[1][nt][1] + acc[1][nt][3] * acc[1][nt][3];
#pragma unroll
        for (int m = 4; m <= 16; m <<= 1) {
            s0 += __shfl_xor_sync(0xFFFFFFFFu, s0, m);
            s1 += __shfl_xor_sync(0xFFFFFFFFu, s1, m);
            q0 += __shfl_xor_sync(0xFFFFFFFFu, q0, m);
            q1 += __shfl_xor_sync(0xFFFFFFFFu, q1, m);
        }
        if (lid < 4) {
            int col = nt * 8 + lid * 2;
            psum[col * 8 + w] = s0;
            psum[(col + 1) * 8 + w] = s1;
            psq[col * 8 + w] = q0;
            psq[(col + 1) * 8 + w] = q1;
        }
    }
    __syncthreads();

    if (tid < FHID) {
        float s = 0.f, qq = 0.f;
#pragma unroll
        for (int j = 0; j < 8; j++) {
            s += psum[tid * 8 + j];
            qq += psq[tid * 8 + j];
        }
        float mean = s * (1.f / BATCH);
        float var = fmaf(-mean, mean, qq * (1.f / BATCH));   // biased variance
        float rstd = rsqrtf(var + 1e-5f);
        float a = gamma[(size_t)c * FHID + tid] * rstd;
        pa[tid] = a;
        pb[tid] = fmaf(-mean, a, beta[(size_t)c * FHID + tid]);
        pw[tid] = W2[(size_t)c * FHID + tid];
    }
    __syncthreads();

    // Transform + per-row dot: rows (w*32 + mt*16 + g_, +8)
    float rd0 = 0.f, rd1 = 0.f, rd2 = 0.f, rd3 = 0.f;
#pragma unroll
    for (int nt = 0; nt < 24; nt++) {
        int col = nt * 8 + (lid & 3) * 2;
        float a0 = pa[col], a1 = pa[col + 1];
        float b0 = pb[col], b1 = pb[col + 1];
        float w0 = pw[col], w1 = pw[col + 1];
        rd0 = fmaf(fmaxf(fmaf(a0, acc[0][nt][0], b0), 0.f), w0,
              fmaf(fmaxf(fmaf(a1, acc[0][nt][1], b1), 0.f), w1, rd0));
        rd1 = fmaf(fmaxf(fmaf(a0, acc[0][nt][2], b0), 0.f), w0,
              fmaf(fmaxf(fmaf(a1, acc[0][nt][3], b1), 0.f), w1, rd1));
        rd2 = fmaf(fmaxf(fmaf(a0, acc[1][nt][0], b0), 0.f), w0,
              fmaf(fmaxf(fmaf(a1, acc[1][nt][1], b1), 0.f), w1, rd2));
        rd3 = fmaf(fmaxf(fmaf(a0, acc[1][nt][2], b0), 0.f), w0,
              fmaf(fmaxf(fmaf(a1, acc[1][nt][3], b1), 0.f), w1, rd3));
    }
#pragma unroll
    for (int m = 1; m <= 2; m <<= 1) {
        rd0 += __shfl_xor_sync(0xFFFFFFFFu, rd0, m);
        rd1 += __shfl_xor_sync(0xFFFFFFFFu, rd1, m);
        rd2 += __shfl_xor_sync(0xFFFFFFFFu, rd2, m);
        rd3 += __shfl_xor_sync(0xFFFFFFFFu, rd3, m);
    }
    if ((lid & 3) == 0) {
        float b2c = b2[c];
        int r0 = w * 32 + g_;
        out[(size_t)(r0)      * CELLS + c] = rd0 + b2c;
        out[(size_t)(r0 + 8)  * CELLS + c] = rd1 + b2c;
        out[(size_t)(r0 + 16) * CELLS + c] = rd2 + b2c;
        out[(size_t)(r0 + 24) * CELLS + c] = rd3 + b2c;
    }
}

extern "C" void kernel_launch(void* const* d_in, const int* in_sizes, int n_in,
                              void* d_out, int out_size) {
    const float* x     = (const float*)d_in[0];
    const float* W1    = (const float*)d_in[1];
    const float* gamma = (const float*)d_in[2];
    const float* beta  = (const float*)d_in[3];
    const float* W2    = (const float*)d_in[4];
    const float* b2    = (const float*)d_in[5];
    float* out = (float*)d_out;
    (void)in_sizes; (void)n_in; (void)out_size;

    cudaFuncSetAttribute(mmlp_kernel, cudaFuncAttributeMaxDynamicSharedMemorySize,
                         SMEM_TOTAL);
    mmlp_kernel<<<CELLS, 256, SMEM_TOTAL>>>(x, W1, gamma, beta, W2, b2, out);
}

// round 17
// speedup vs baseline: 2.1144x; 1.1203x over previous
#include <cuda_runtime.h>
#include <cstdint>

// Problem constants (fixed shapes)
#define CELLS 4096
#define BATCH 256
#define FIN   160
#define FHID  192
#define KC    32          // K-chunk (5 chunks of 32 = 160); 4 k8-steps each
#define NCHUNK 5

// fp32 operand buffers (staged by cp.async, consumed by ldmatrix; tf32
// rounding happens in registers). Double buffered. Row stride 144 B
// (36 floats: 32 data + 4 pad) -> conflict-free ldmatrix (banks 4r..4r+3).
#define SSTRIDE 144
#define ABASE 0                          // A: 256 rows
#define BBASE (256 * SSTRIDE)            // 36864 : B: 192 rows
#define BUFSZ (BBASE + 192 * SSTRIDE)    // 64512
#define SMEM_TOTAL (2 * BUFSZ)           // 129024

// epilogue scratch reuses buffer 0 (after the post-mainloop barrier)
#define SM_PSUM 0                        // float[192][4]
#define SM_PSQ  3072                     // float[192][4]
#define SM_PA   6144                     // float[192]
#define SM_PB   (SM_PA + 768)
#define SM_PW   (SM_PB + 768)
#define SM_PD   (SM_PW + 768)            // float[256][2]

// m16n8k8 tf32 MMA, fp32 accumulate (sm_80+, assembles on compute_103)
#define MMA(d, a, b0, b1)                                                    \
    asm volatile(                                                            \
        "mma.sync.aligned.m16n8k8.row.col.f32.tf32.tf32.f32 "                \
        "{%0,%1,%2,%3}, {%4,%5,%6,%7}, {%8,%9}, {%0,%1,%2,%3};"              \
        : "+f"((d)[0]), "+f"((d)[1]), "+f"((d)[2]), "+f"((d)[3])             \
        : "r"((a)[0]), "r"((a)[1]), "r"((a)[2]), "r"((a)[3]),                \
          "r"(b0), "r"(b1))

#define LDM4(r, a)                                                           \
    asm volatile("ldmatrix.sync.aligned.m8n8.x4.shared.b16 {%0,%1,%2,%3}, [%4];" \
        : "=r"((r)[0]), "=r"((r)[1]), "=r"((r)[2]), "=r"((r)[3]) : "r"(a))

#define CPASYNC16(dst, src)                                                  \
    asm volatile("cp.async.cg.shared.global [%0], [%1], 16;"                 \
        :: "r"(dst), "l"(src) : "memory")
#define CPCOMMIT() asm volatile("cp.async.commit_group;" ::: "memory")
#define CPWAIT(n)  asm volatile("cp.async.wait_group %0;" :: "n"(n) : "memory")

static __device__ __forceinline__ unsigned smem_u32(const void* p) {
    unsigned a;
    asm("{ .reg .u64 t; cvta.to.shared.u64 t, %1; cvt.u32.u64 %0, t; }"
        : "=r"(a) : "l"(p));
    return a;
}

// tf32 RNA rounding on fp32 bits held in an unsigned reg (idempotent)
static __device__ __forceinline__ unsigned tf32r(unsigned bits) {
    unsigned u;
    asm("cvt.rna.tf32.f32 %0, %1;" : "=r"(u) : "f"(__uint_as_float(bits)));
    return u;
}

__global__ void __launch_bounds__(256, 1)
mmlp_kernel(const float* __restrict__ x, const float* __restrict__ W1,
            const float* __restrict__ gamma, const float* __restrict__ beta,
            const float* __restrict__ W2, const float* __restrict__ b2,
            float* __restrict__ out) {
    extern __shared__ char smem[];
    const unsigned sb = smem_u32(smem);
    const int tid = threadIdx.x;
    const int lid = tid & 31;
    const int w   = tid >> 5;          // 8 warps: 4 (M) x 2 (N)
    const int gm  = w >> 1;            // m-block: rows [64*gm, 64*gm+64)
    const int nh  = w & 1;             // n-half: cols [96*nh, 96*nh+96)
    const int c   = blockIdx.x;
    const int g_  = lid >> 2;

    // cp.async issue for chunk k into buffer (k & 1)
    auto issue_chunk = [&](int k) {
        const unsigned bb = sb + (unsigned)(k & 1) * BUFSZ;
        const float* xs = x + c * (size_t)FIN + k * KC;
        const float* ws = W1 + (size_t)c * FHID * FIN + k * KC;
#pragma unroll
        for (int q = 0; q < 8; q++) {              // A: 2048 16B segs
            int s = tid + q * 256;
            int row = s >> 3, seg = s & 7;
            CPASYNC16(bb + ABASE + row * SSTRIDE + seg * 16,
                      xs + (size_t)row * (CELLS * FIN) + seg * 4);
        }
#pragma unroll
        for (int q = 0; q < 6; q++) {              // B: 1536 16B segs
            int s = tid + q * 256;
            int row = s >> 3, seg = s & 7;
            CPASYNC16(bb + BBASE + row * SSTRIDE + seg * 16,
                      ws + (size_t)row * FIN + seg * 4);
        }
    };

    // C accumulators: warp tile 64(M) x 96(N) -> 4 m16-tiles x 12 n8-tiles x 4
    float acc[4][12][4];
#pragma unroll
    for (int mt = 0; mt < 4; mt++)
#pragma unroll
        for (int nt = 0; nt < 12; nt++)
#pragma unroll
            for (int j = 0; j < 4; j++) acc[mt][nt][j] = 0.f;

    // ldmatrix lane addressing for tf32 fragments (b16-pair trick, proven R15)
    const int arow = (lid & 7) + ((lid >> 3) & 1) * 8;
    const unsigned akoff = (unsigned)(((lid >> 4) & 1) * 16);
    const int brow = ((lid >> 4) & 1) * 8 + (lid & 7);
    const unsigned bkoff = (unsigned)(((lid >> 3) & 1) * 16);

    // ---- Prologue: stage chunks 0 and 1 ----
    issue_chunk(0); CPCOMMIT();
    issue_chunk(1); CPCOMMIT();
    CPWAIT(1);                          // own chunk-0 copies complete
    __syncthreads();                    // all threads' chunk-0 data visible

    // ---- Mainloop: MMA(chunk i, buf i&1); cp.async(chunk i+2) behind it ----
#pragma unroll 1
    for (int i = 0; i < NCHUNK; i++) {
        const unsigned cb = sb + (unsigned)(i & 1) * BUFSZ;
#pragma unroll
        for (int ks = 0; ks < 4; ks++) {           // k8 steps within chunk
            unsigned a[4][4];
            unsigned ka = cb + ABASE +
                          (unsigned)((gm * 64 + arow) * SSTRIDE) +
                          akoff + ks * 32;
#pragma unroll
            for (int mt = 0; mt < 4; mt++) {
                LDM4(a[mt], ka + mt * 16 * SSTRIDE);
#pragma unroll
                for (int r = 0; r < 4; r++) a[mt][r] = tf32r(a[mt][r]);
            }
#pragma unroll
            for (int jp = 0; jp < 6; jp++) {       // nt pairs (2jp, 2jp+1)
                unsigned b[4];
                unsigned kb = cb + BBASE +
                              (unsigned)((nh * 96 + jp * 16 + brow) * SSTRIDE) +
                              bkoff + ks * 32;
                LDM4(b, kb);
#pragma unroll
                for (int r = 0; r < 4; r++) b[r] = tf32r(b[r]);
#pragma unroll
                for (int mt = 0; mt < 4; mt++) {
                    MMA(acc[mt][2 * jp],     a[mt], b[0], b[1]);
                    MMA(acc[mt][2 * jp + 1], a[mt], b[2], b[3]);
                }
            }
        }
        if (i + 1 < NCHUNK) {
            __syncthreads();            // all reads of buf(i&1) done
            if (i + 2 < NCHUNK) {
                issue_chunk(i + 2);     // refill buf(i&1)
                CPCOMMIT();
                CPWAIT(1);              // own chunk i+1 copies complete
            } else {
                CPWAIT(0);
            }
            __syncthreads();            // chunk i+1 data visible to all
        }
    }
    __syncthreads();   // all MMA reads of buf0 done before scratch reuse

    // ---- Epilogue: BN stats + folded BN + relu + W2 dot ----
    float* psum = reinterpret_cast<float*>(smem + SM_PSUM);
    float* psq  = reinterpret_cast<float*>(smem + SM_PSQ);
    float* pa   = reinterpret_cast<float*>(smem + SM_PA);
    float* pb   = reinterpret_cast<float*>(smem + SM_PB);
    float* pw   = reinterpret_cast<float*>(smem + SM_PW);
    float* pd   = reinterpret_cast<float*>(smem + SM_PD);

    // Per-column partial sums over this warp's 64 rows
#pragma unroll
    for (int nt = 0; nt < 12; nt++) {
        float s0 = 0.f, s1 = 0.f, q0 = 0.f, q1 = 0.f;
#pragma unroll
        for (int mt = 0; mt < 4; mt++) {
            s0 += acc[mt][nt][0] + acc[mt][nt][2];
            s1 += acc[mt][nt][1] + acc[mt][nt][3];
            q0 += acc[mt][nt][0] * acc[mt][nt][0] + acc[mt][nt][2] * acc[mt][nt][2];
            q1 += acc[mt][nt][1] * acc[mt][nt][1] + acc[mt][nt][3] * acc[mt][nt][3];
        }
#pragma unroll
        for (int m = 4; m <= 16; m <<= 1) {
            s0 += __shfl_xor_sync(0xFFFFFFFFu, s0, m);
            s1 += __shfl_xor_sync(0xFFFFFFFFu, s1, m);
            q0 += __shfl_xor_sync(0xFFFFFFFFu, q0, m);
            q1 += __shfl_xor_sync(0xFFFFFFFFu, q1, m);
        }
        if (lid < 4) {
            int col = nh * 96 + nt * 8 + lid * 2;  // global column
            psum[col * 4 + gm] = s0;
            psum[(col + 1) * 4 + gm] = s1;
            psq[col * 4 + gm] = q0;
            psq[(col + 1) * 4 + gm] = q1;
        }
    }
    __syncthreads();

    if (tid < FHID) {
        float s = psum[tid * 4] + psum[tid * 4 + 1] +
                  psum[tid * 4 + 2] + psum[tid * 4 + 3];
        float qq = psq[tid * 4] + psq[tid * 4 + 1] +
                   psq[tid * 4 + 2] + psq[tid * 4 + 3];
        float mean = s * (1.f / BATCH);
        float var = fmaf(-mean, mean, qq * (1.f / BATCH));   // biased variance
        float rstd = rsqrtf(var + 1e-5f);
        float a = gamma[(size_t)c * FHID + tid] * rstd;
        pa[tid] = a;
        pb[tid] = fmaf(-mean, a, beta[(size_t)c * FHID + tid]);
        pw[tid] = W2[(size_t)c * FHID + tid];
    }
    __syncthreads();

    // Transform + per-row partial dot over this warp's 96 columns
    float rd[4][2];
#pragma unroll
    for (int mt = 0; mt < 4; mt++) { rd[mt][0] = 0.f; rd[mt][1] = 0.f; }
#pragma unroll
    for (int nt = 0; nt < 12; nt++) {
        int col = nh * 96 + nt * 8 + (lid & 3) * 2;
        float a0 = pa[col], a1 = pa[col + 1];
        float b0 = pb[col], b1 = pb[col + 1];
        float w0 = pw[col], w1 = pw[col + 1];
#pragma unroll
        for (int mt = 0; mt < 4; mt++) {
            rd[mt][0] = fmaf(fmaxf(fmaf(a0, acc[mt][nt][0], b0), 0.f), w0,
                        fmaf(fmaxf(fmaf(a1, acc[mt][nt][1], b1), 0.f), w1,
                             rd[mt][0]));
            rd[mt][1] = fmaf(fmaxf(fmaf(a0, acc[mt][nt][2], b0), 0.f), w0,
                        fmaf(fmaxf(fmaf(a1, acc[mt][nt][3], b1), 0.f), w1,
                             rd[mt][1]));
        }
    }
#pragma unroll
    for (int m = 1; m <= 2; m <<= 1)
#pragma unroll
        for (int mt = 0; mt < 4; mt++) {
            rd[mt][0] += __shfl_xor_sync(0xFFFFFFFFu, rd[mt][0], m);
            rd[mt][1] += __shfl_xor_sync(0xFFFFFFFFu, rd[mt][1], m);
        }
    if ((lid & 3) == 0) {
#pragma unroll
        for (int mt = 0; mt < 4; mt++) {
            int r0 = gm * 64 + mt * 16 + g_;
            pd[(r0)     * 2 + nh] = rd[mt][0];
            pd[(r0 + 8) * 2 + nh] = rd[mt][1];
        }
    }
    __syncthreads();

    if (tid < BATCH) {
        out[(size_t)tid * CELLS + c] = pd[tid * 2] + pd[tid * 2 + 1] + b2[c];
    }
}

extern "C" void kernel_launch(void* const* d_in, const int* in_sizes, int n_in,
                              void* d_out, int out_size) {
    const float* x     = (const float*)d_in[0];
    const float* W1    = (const float*)d_in[1];
    const float* gamma = (const float*)d_in[2];
    const float* beta  = (const float*)d_in[3];
    const float* W2    = (const float*)d_in[4];
    const float* b2    = (const float*)d_in[5];
    float* out = (float*)d_out;
    (void)in_sizes; (void)n_in; (void)out_size;

    cudaFuncSetAttribute(mmlp_kernel, cudaFuncAttributeMaxDynamicSharedMemorySize,
                         SMEM_TOTAL);
    mmlp_kernel<<<CELLS, 256, SMEM_TOTAL>>>(x, W1, gamma, beta, W2, b2, out);
}